// round 8
// baseline (speedup 1.0000x reference)
#include <cuda_runtime.h>
#include <cuda_fp16.h>
#include <math.h>
#include <stdint.h>

// ---------------- problem constants ----------------
#define B_ 4
#define T_ 4096
#define F_ 131           // 1 mean + 128 z + 1 v + 1 noise
#define D_ 128
#define NT64 64          // j tiles of 64
#define NPAIR2 1056      // sum_{ti=0..31} (64 - 2*ti)
#define JITTER_ 1e-6f

// per-row precomputed: w = exp(-sq/256)*v ; nsp = softplus(noise)
__device__ float g_w[B_ * T_];
__device__ float g_nsp[B_ * T_];

// ---------------- SMEM layout ----------------
// fp16 tiles, 272-byte row stride (136 halfs)
#define TROWB 272
#define A_OFF 0
#define A_BYTES (128 * TROWB)            // 34816
#define B_OFF A_BYTES
#define B_BYTES (64 * TROWB)             // 17408
#define SMEM_BYTES (A_BYTES + B_BYTES)   // 52224
// stage (reuses tile region): 128 x 65 floats = 33280 B
#define SSTRIDE 65

__device__ __forceinline__ uint32_t smem_u32(const void* p) {
    uint32_t a;
    asm("{ .reg .u64 t; cvta.to.shared.u64 t, %1; cvt.u32.u64 %0, t; }"
        : "=r"(a) : "l"(p));
    return a;
}

#define LDMX4(r0, r1, r2, r3, addr)                                        \
    asm volatile("ldmatrix.sync.aligned.m8n8.x4.shared.b16 {%0,%1,%2,%3}, [%4];" \
                 : "=r"(r0), "=r"(r1), "=r"(r2), "=r"(r3) : "r"(addr))

#define MMA16816(c, a0, a1, a2, a3, b0, b1)                                \
    asm volatile(                                                          \
        "mma.sync.aligned.m16n8k16.row.col.f32.f16.f16.f32 "               \
        "{%0,%1,%2,%3}, {%4,%5,%6,%7}, {%8,%9}, {%0,%1,%2,%3};"            \
        : "+f"((c)[0]), "+f"((c)[1]), "+f"((c)[2]), "+f"((c)[3])           \
        : "r"(a0), "r"(a1), "r"(a2), "r"(a3), "r"(b0), "r"(b1))

__device__ __forceinline__ void stg_cs(float* p, float v) {
    asm volatile("st.global.cs.f32 [%0], %1;" :: "l"(p), "f"(v) : "memory");
}

__device__ __forceinline__ float ex2f(float x) {
    float y;
    asm("ex2.approx.ftz.f32 %0, %1;" : "=f"(y) : "f"(x));
    return y;
}

__device__ __forceinline__ uint32_t pack_h2(float x0, float x1) {
    __half h0 = __float2half_rn(x0);
    __half h1 = __float2half_rn(x1);
    return (uint32_t)__half_as_ushort(h0) | ((uint32_t)__half_as_ushort(h1) << 16);
}

// ---------------- prologue ----------------
__global__ void __launch_bounds__(256) pre_kernel(const float* __restrict__ in,
                                                  float* __restrict__ mean_out) {
    int warp = (blockIdx.x * blockDim.x + threadIdx.x) >> 5;
    int lane = threadIdx.x & 31;
    if (warp >= B_ * T_) return;
    const float* row = in + (size_t)warp * F_;
    float s = 0.f;
#pragma unroll
    for (int k = 0; k < 4; k++) {
        float z = row[1 + lane + 32 * k];
        s += z * z;
    }
#pragma unroll
    for (int off = 16; off; off >>= 1) s += __shfl_xor_sync(0xffffffffu, s, off);
    if (lane == 0) {
        float v = row[1 + D_];
        float noise = row[F_ - 1];
        g_w[warp] = exp2f(-s * 0.0056355275034725f) * v;  // exp(-s/256)*v
        g_nsp[warp] = fmaxf(noise, 0.f) + log1pf(__expf(-fabsf(noise)));
        mean_out[warp] = row[0];
    }
}

// ---------------- main kernel: 128 threads, 128(i) x 64(j) tile ----------------
extern __shared__ char smem[];

__global__ void __launch_bounds__(128, 4) cov_kernel(const float* __restrict__ in,
                                                     float* __restrict__ fcov,
                                                     float* __restrict__ ycov) {
    const int b = blockIdx.y;
    int u = blockIdx.x;
    int ti = 0;
    while (u >= NT64 - 2 * ti) { u -= NT64 - 2 * ti; ti++; }
    const int tjj = 2 * ti + u;           // j tile (64-wide), tjj >= 2*ti
    const int i0 = ti * 128;
    const int j0 = tjj * 64;
    const bool diagish = (tjj >> 1) == ti;  // j-tile inside the i-strip
    const int dj = j0 - i0;                 // 0 or 64 when diagish

    const int tid = threadIdx.x;
    const int wid = tid >> 5;
    const int lane = tid & 31;
    const uint32_t sb = smem_u32(smem);

    // ---- load + fp16 convert into SMEM ----
    const float* base = in + (size_t)b * T_ * F_;
#pragma unroll 4
    for (int it = 0; it < 64; it++) {      // A: 128 rows x 64 col-pairs
        int p = it * 128 + tid;
        int r = p >> 6;
        int c2 = (p & 63) * 2;
        const float* rp = base + (uint32_t)((i0 + r) * F_ + 1 + c2);
        *(uint32_t*)(smem + A_OFF + (uint32_t)(r * TROWB + c2 * 2)) =
            pack_h2(__ldg(rp), __ldg(rp + 1));
    }
#pragma unroll 4
    for (int it = 0; it < 32; it++) {      // B: 64 rows x 64 col-pairs
        int p = it * 128 + tid;
        int r = p >> 6;
        int c2 = (p & 63) * 2;
        const float* rp = base + (uint32_t)((j0 + r) * F_ + 1 + c2);
        *(uint32_t*)(smem + B_OFF + (uint32_t)(r * TROWB + c2 * 2)) =
            pack_h2(__ldg(rp), __ldg(rp + 1));
    }
    __syncthreads();

    // ---- MMA: warp tile 64(m) x 32(n) ----
    const int m0 = (wid & 1) * 64;
    const int n0 = (wid >> 1) * 32;

    float acc[4][4][4];
#pragma unroll
    for (int a = 0; a < 4; a++)
#pragma unroll
        for (int n = 0; n < 4; n++)
#pragma unroll
            for (int q = 0; q < 4; q++) acc[a][n][q] = 0.f;

    const uint32_t aRowByte = (uint32_t)((m0 + (lane & 15)) * TROWB +
                                         ((lane >> 4) * 8) * 2);
    const uint32_t bRowByte =
        (uint32_t)((n0 + (lane & 7) + ((lane >> 4) << 3)) * TROWB +
                   (((lane >> 3) & 1) * 8) * 2);

#pragma unroll 1
    for (int ks = 0; ks < 8; ks++) {
        const uint32_t koff = (uint32_t)(ks * 32);
        uint32_t ra[4][4];
#pragma unroll
        for (int a = 0; a < 4; a++) {
            uint32_t addr = sb + A_OFF + aRowByte + a * 16 * TROWB + koff;
            LDMX4(ra[a][0], ra[a][1], ra[a][2], ra[a][3], addr);
        }
#pragma unroll
        for (int nt = 0; nt < 2; nt++) {
            uint32_t rb[4];
            uint32_t addr = sb + B_OFF + bRowByte + nt * 16 * TROWB + koff;
            LDMX4(rb[0], rb[1], rb[2], rb[3], addr);
#pragma unroll
            for (int a = 0; a < 4; a++) {
                MMA16816(acc[a][2 * nt], ra[a][0], ra[a][1], ra[a][2], ra[a][3],
                         rb[0], rb[1]);
                MMA16816(acc[a][2 * nt + 1], ra[a][0], ra[a][1], ra[a][2],
                         ra[a][3], rb[2], rb[3]);
            }
        }
    }
    __syncthreads();   // tiles consumed; stage region is free

    // ---- epilogue: f = exp2(g*SC) * w_i * w_j -> SMEM stage ----
    const int bT = b * T_;
    const float SC = 0.011271055006945f;  // log2(e)/128
    float* stage = (float*)smem;          // [128][65]

    const int rA = lane >> 2;             // 0..7
    const int cQ = 2 * (lane & 3);        // 0,2,4,6

    float wi[4][2], wj[4][2];
#pragma unroll
    for (int a = 0; a < 4; a++)
#pragma unroll
        for (int h = 0; h < 2; h++)
            wi[a][h] = __ldg(g_w + bT + i0 + m0 + a * 16 + rA + h * 8);
#pragma unroll
    for (int nn = 0; nn < 4; nn++)
#pragma unroll
        for (int e = 0; e < 2; e++)
            wj[nn][e] = __ldg(g_w + bT + j0 + n0 + nn * 8 + cQ + e);

#pragma unroll
    for (int a = 0; a < 4; a++) {
#pragma unroll
        for (int nn = 0; nn < 4; nn++) {
            const int r1 = m0 + a * 16 + rA;
            const int c = n0 + nn * 8 + cQ;
#pragma unroll
            for (int q = 0; q < 4; q++) {
                float f = ex2f(acc[a][nn][q] * SC) * wi[a][q >> 1] * wj[nn][q & 1];
                stage[(r1 + (q >> 1) * 8) * SSTRIDE + c + (q & 1)] = f;
            }
        }
    }
    __syncthreads();

    // ---- store: direct tile (rows i0.., cols j0..) ----
    const uint32_t matBase = (uint32_t)b * (uint32_t)(T_ * T_);
#pragma unroll 1
    for (int it = 0; it < 32; it++) {
        int r = it * 4 + wid;             // 0..127
        uint32_t rowOff = matBase + (uint32_t)(i0 + r) * T_ + (uint32_t)(j0 + lane);
        float* fp = fcov + rowOff;
        float* yp = ycov + rowOff;
        if (diagish) {
            float nsp = __ldg(g_nsp + bT + i0 + r);
            int cd = r - dj;              // diagonal column (if in [0,64))
#pragma unroll
            for (int k = 0; k < 2; k++) {
                int c = lane + 32 * k;
                float f = stage[r * SSTRIDE + c];
                float y = f;
                if (c == cd) {
                    f += JITTER_;
                    y += JITTER_ + nsp;
                }
                stg_cs(fp + 32 * k, f);
                stg_cs(yp + 32 * k, y);
            }
        } else {
#pragma unroll
            for (int k = 0; k < 2; k++) {
                float f = stage[r * SSTRIDE + lane + 32 * k];
                stg_cs(fp + 32 * k, f);
                stg_cs(yp + 32 * k, f);
            }
        }
    }

    // ---- mirror tile (rows j0..j0+64, cols i0..i0+128); skip for diagish ----
    if (!diagish) {
#pragma unroll 1
        for (int it = 0; it < 16; it++) {
            int r = it * 4 + wid;         // 0..63 (mirror row within j-tile)
            uint32_t rowOff =
                matBase + (uint32_t)(j0 + r) * T_ + (uint32_t)(i0 + lane);
            float* fp = fcov + rowOff;
            float* yp = ycov + rowOff;
#pragma unroll
            for (int k = 0; k < 4; k++) {
                float f = stage[(lane + 32 * k) * SSTRIDE + r];
                stg_cs(fp + 32 * k, f);
                stg_cs(yp + 32 * k, f);
            }
        }
    }
}

// ---------------- launch ----------------
extern "C" void kernel_launch(void* const* d_in, const int* in_sizes, int n_in,
                              void* d_out, int out_size) {
    const float* in = (const float*)d_in[0];
    float* out = (float*)d_out;
    float* mean = out;
    float* fcov = out + (size_t)B_ * T_;
    float* ycov = fcov + (size_t)B_ * T_ * T_;

    pre_kernel<<<(B_ * T_ * 32 + 255) / 256, 256>>>(in, mean);

    static int configured = 0;
    if (!configured) {
        cudaFuncSetAttribute(cov_kernel, cudaFuncAttributeMaxDynamicSharedMemorySize,
                             SMEM_BYTES);
        configured = 1;
    }
    dim3 grid(NPAIR2, B_);
    cov_kernel<<<grid, 128, SMEM_BYTES>>>(in, fcov, ycov);
}

// round 9
// speedup vs baseline: 1.0971x; 1.0971x over previous
#include <cuda_runtime.h>
#include <cuda_fp16.h>
#include <math.h>
#include <stdint.h>

// ---------------- problem constants ----------------
#define B_ 4
#define T_ 4096
#define F_ 131           // 1 mean + 128 z + 1 v + 1 noise
#define D_ 128
#define NT 32            // 128-row tiles per dim
#define NPAIR 528        // NT*(NT+1)/2
#define NWORK (NPAIR * B_)  // 2112
#define JITTER_ 1e-6f

__device__ float g_w[B_ * T_];
__device__ float g_nsp[B_ * T_];

// ---------------- SMEM layout (bytes) ----------------
#define TROW 136                         // halfs per tile row (272 B)
#define TILE_BYTES (128 * TROW * 2)      // 34816
#define A_OFF 0
#define B_OFF TILE_BYTES
#define STAGE0_OFF (2 * TILE_BYTES)      // 69632
#define SSTRIDE 129                      // floats; conflict-free rows AND cols
#define STAGE_BYTES (128 * SSTRIDE * 4)  // 66048
#define STAGE1_OFF (STAGE0_OFF + STAGE_BYTES)
#define MBAR_OFF (STAGE1_OFF + STAGE_BYTES)   // 201728
#define SMEM_BYTES (MBAR_OFF + 64)
// mbar layout: full0 @ +0, full1 @ +8, empty0 @ +16, empty1 @ +24

__device__ __forceinline__ uint32_t smem_u32(const void* p) {
    uint32_t a;
    asm("{ .reg .u64 t; cvta.to.shared.u64 t, %1; cvt.u32.u64 %0, t; }"
        : "=r"(a) : "l"(p));
    return a;
}

#define LDMX4(r0, r1, r2, r3, addr)                                        \
    asm volatile("ldmatrix.sync.aligned.m8n8.x4.shared.b16 {%0,%1,%2,%3}, [%4];" \
                 : "=r"(r0), "=r"(r1), "=r"(r2), "=r"(r3) : "r"(addr))

#define MMA16816(c, a0, a1, a2, a3, b0, b1)                                \
    asm volatile(                                                          \
        "mma.sync.aligned.m16n8k16.row.col.f32.f16.f16.f32 "               \
        "{%0,%1,%2,%3}, {%4,%5,%6,%7}, {%8,%9}, {%0,%1,%2,%3};"            \
        : "+f"((c)[0]), "+f"((c)[1]), "+f"((c)[2]), "+f"((c)[3])           \
        : "r"(a0), "r"(a1), "r"(a2), "r"(a3), "r"(b0), "r"(b1))

__device__ __forceinline__ void stg_cs(float* p, float v) {
    asm volatile("st.global.cs.f32 [%0], %1;" :: "l"(p), "f"(v) : "memory");
}
__device__ __forceinline__ float ex2f(float x) {
    float y;
    asm("ex2.approx.ftz.f32 %0, %1;" : "=f"(y) : "f"(x));
    return y;
}
__device__ __forceinline__ uint32_t pack_h2(float x0, float x1) {
    __half h0 = __float2half_rn(x0);
    __half h1 = __float2half_rn(x1);
    return (uint32_t)__half_as_ushort(h0) | ((uint32_t)__half_as_ushort(h1) << 16);
}

#define MBAR_INIT(a, n) \
    asm volatile("mbarrier.init.shared.b64 [%0], %1;" :: "r"(a), "r"(n) : "memory")
#define MBAR_ARRIVE(a) \
    asm volatile("mbarrier.arrive.shared.b64 _, [%0];" :: "r"(a) : "memory")

__device__ __forceinline__ void mbar_wait(uint32_t mbar, uint32_t parity) {
    uint32_t done;
    asm volatile(
        "{\n\t.reg .pred p;\n\t"
        "mbarrier.try_wait.parity.acquire.cta.shared::cta.b64 p, [%1], %2;\n\t"
        "selp.b32 %0, 1, 0, p;\n\t}"
        : "=r"(done) : "r"(mbar), "r"(parity) : "memory");
    if (!done) {
        asm volatile(
            "{\n\t.reg .pred P1;\n\t"
            "WAIT_LOOP_%=:\n\t"
            "mbarrier.try_wait.parity.acquire.cta.shared::cta.b64 P1, [%0], %1, 0x989680;\n\t"
            "@P1 bra.uni WAIT_DONE_%=;\n\t"
            "bra.uni WAIT_LOOP_%=;\n\t"
            "WAIT_DONE_%=:\n\t}"
            :: "r"(mbar), "r"(parity) : "memory");
    }
}

// producer-group barrier (warps 0-7 = threads 0-255)
#define PROD_SYNC() asm volatile("bar.sync 1, 256;" ::: "memory")

// ---------------- prologue ----------------
__global__ void __launch_bounds__(256) pre_kernel(const float* __restrict__ in,
                                                  float* __restrict__ mean_out) {
    int warp = (blockIdx.x * blockDim.x + threadIdx.x) >> 5;
    int lane = threadIdx.x & 31;
    if (warp >= B_ * T_) return;
    const float* row = in + (size_t)warp * F_;
    float s = 0.f;
#pragma unroll
    for (int k = 0; k < 4; k++) {
        float z = row[1 + lane + 32 * k];
        s += z * z;
    }
#pragma unroll
    for (int off = 16; off; off >>= 1) s += __shfl_xor_sync(0xffffffffu, s, off);
    if (lane == 0) {
        float v = row[1 + D_];
        float noise = row[F_ - 1];
        g_w[warp] = exp2f(-s * 0.0056355275034725f) * v;  // exp(-s/256)*v
        g_nsp[warp] = fmaxf(noise, 0.f) + log1pf(__expf(-fabsf(noise)));
        mean_out[warp] = row[0];
    }
}

// decode linear work index -> (b, ti, tj)
__device__ __forceinline__ void decode_work(int idx, int& b, int& ti, int& tj) {
    b = idx / NPAIR;
    int u = idx - b * NPAIR;
    ti = 0;
    while (u >= NT - ti) { u -= NT - ti; ti++; }
    tj = ti + u;
}

// ---------------- persistent warp-specialized kernel ----------------
extern __shared__ char smem[];

__global__ void __launch_bounds__(512, 1) cov_kernel(const float* __restrict__ in,
                                                     float* __restrict__ fcov,
                                                     float* __restrict__ ycov) {
    const int tid = threadIdx.x;
    const int wid = tid >> 5;
    const int lane = tid & 31;
    const uint32_t sb = smem_u32(smem);
    const uint32_t mb = sb + MBAR_OFF;

    if (tid == 0) {
        MBAR_INIT(mb + 0, 256);   // full[0]
        MBAR_INIT(mb + 8, 256);   // full[1]
        MBAR_INIT(mb + 16, 256);  // empty[0]
        MBAR_INIT(mb + 24, 256);  // empty[1]
    }
    __syncthreads();

    int s = 0;
    const bool producer = (wid < 8);
    int ph = producer ? 1 : 0;    // producer waits empty (starts ready)

    if (producer) {
        // ---------------- PRODUCER: load -> MMA -> epilogue into stage ----
        const int m0 = (wid & 3) * 32;
        const int n0 = (wid >> 2) * 64;
        const uint32_t aRowByte = (uint32_t)((m0 + (lane & 15)) * (TROW * 2) +
                                             ((lane >> 4) * 8) * 2);
        const uint32_t bRowByte =
            (uint32_t)((n0 + (lane & 7) + ((lane >> 4) << 3)) * (TROW * 2) +
                       (((lane >> 3) & 1) * 8) * 2);
        const int rA = lane >> 2;
        const int cQ = 2 * (lane & 3);

        for (int idx = blockIdx.x; idx < NWORK; idx += gridDim.x) {
            int b, ti, tj;
            decode_work(idx, b, ti, tj);
            const int i0 = ti * 128, j0 = tj * 128;
            const float* base = in + (size_t)b * T_ * F_;

            // ---- tile load (256 producer threads) ----
#pragma unroll 4
            for (int it = 0; it < 32; it++) {
                int p = it * 256 + tid;
                int r = p >> 6;
                int c2 = (p & 63) * 2;
                uint32_t soff = (uint32_t)(r * (TROW * 2) + c2 * 2);
                {
                    const float* rp = base + (uint32_t)((i0 + r) * F_ + 1 + c2);
                    *(uint32_t*)(smem + A_OFF + soff) =
                        pack_h2(__ldg(rp), __ldg(rp + 1));
                }
                {
                    const float* rp = base + (uint32_t)((j0 + r) * F_ + 1 + c2);
                    *(uint32_t*)(smem + B_OFF + soff) =
                        pack_h2(__ldg(rp), __ldg(rp + 1));
                }
            }
            PROD_SYNC();

            // ---- MMA ----
            float acc[2][8][4];
#pragma unroll
            for (int a = 0; a < 2; a++)
#pragma unroll
                for (int n = 0; n < 8; n++)
#pragma unroll
                    for (int q = 0; q < 4; q++) acc[a][n][q] = 0.f;

#pragma unroll 1
            for (int ks = 0; ks < 8; ks++) {
                const uint32_t koff = (uint32_t)(ks * 32);
                uint32_t ra[2][4];
#pragma unroll
                for (int a = 0; a < 2; a++) {
                    uint32_t addr = sb + A_OFF + aRowByte + a * 16 * (TROW * 2) + koff;
                    LDMX4(ra[a][0], ra[a][1], ra[a][2], ra[a][3], addr);
                }
#pragma unroll
                for (int nt = 0; nt < 4; nt++) {
                    uint32_t rb[4];
                    uint32_t addr = sb + B_OFF + bRowByte + nt * 16 * (TROW * 2) + koff;
                    LDMX4(rb[0], rb[1], rb[2], rb[3], addr);
#pragma unroll
                    for (int a = 0; a < 2; a++) {
                        MMA16816(acc[a][2 * nt], ra[a][0], ra[a][1], ra[a][2],
                                 ra[a][3], rb[0], rb[1]);
                        MMA16816(acc[a][2 * nt + 1], ra[a][0], ra[a][1], ra[a][2],
                                 ra[a][3], rb[2], rb[3]);
                    }
                }
            }
            PROD_SYNC();   // tiles fully consumed before next-iter load

            // ---- epilogue into stage buffer s ----
            mbar_wait(mb + 16 + 8 * s, ph);   // empty[s]
            {
                const int bT = b * T_;
                const float SC = 0.011271055006945f;  // log2(e)/128
                float* stage =
                    (float*)(smem + (s ? STAGE1_OFF : STAGE0_OFF));
                float wi[2][2], wj[8][2];
#pragma unroll
                for (int a = 0; a < 2; a++)
#pragma unroll
                    for (int h = 0; h < 2; h++)
                        wi[a][h] = __ldg(g_w + bT + i0 + m0 + a * 16 + rA + h * 8);
#pragma unroll
                for (int n = 0; n < 8; n++)
#pragma unroll
                    for (int e = 0; e < 2; e++)
                        wj[n][e] = __ldg(g_w + bT + j0 + n0 + n * 8 + cQ + e);

#pragma unroll
                for (int a = 0; a < 2; a++) {
#pragma unroll
                    for (int n = 0; n < 8; n++) {
                        const int r1 = m0 + a * 16 + rA;
                        const int c = n0 + n * 8 + cQ;
#pragma unroll
                        for (int q = 0; q < 4; q++) {
                            float f = ex2f(acc[a][n][q] * SC) * wi[a][q >> 1] *
                                      wj[n][q & 1];
                            stage[(r1 + (q >> 1) * 8) * SSTRIDE + c + (q & 1)] = f;
                        }
                    }
                }
            }
            MBAR_ARRIVE(mb + 0 + 8 * s);      // full[s]
            s ^= 1;
            if (s == 0) ph ^= 1;
        }
    } else {
        // ---------------- CONSUMER: drain stage -> GMEM ----
        const int cw = wid - 8;   // 0..7
        for (int idx = blockIdx.x; idx < NWORK; idx += gridDim.x) {
            int b, ti, tj;
            decode_work(idx, b, ti, tj);
            const int i0 = ti * 128, j0 = tj * 128;
            const bool diag = (ti == tj);
            const int bT = b * T_;
            const uint32_t matBase = (uint32_t)b * (uint32_t)(T_ * T_);

            mbar_wait(mb + 0 + 8 * s, ph);    // full[s]
            const float* stage =
                (const float*)(smem + (s ? STAGE1_OFF : STAGE0_OFF));

            // direct tile rows
#pragma unroll 1
            for (int it = 0; it < 16; it++) {
                int r = it * 8 + cw;
                uint32_t rowOff =
                    matBase + (uint32_t)(i0 + r) * T_ + (uint32_t)(j0 + lane);
                float* fp = fcov + rowOff;
                float* yp = ycov + rowOff;
                if (diag) {
                    float nsp = __ldg(g_nsp + bT + i0 + r);
#pragma unroll
                    for (int k = 0; k < 4; k++) {
                        int c = lane + 32 * k;
                        float f = stage[r * SSTRIDE + c];
                        float y = f;
                        if (c == r) {
                            f += JITTER_;
                            y += JITTER_ + nsp;
                        }
                        stg_cs(fp + 32 * k, f);
                        stg_cs(yp + 32 * k, y);
                    }
                } else {
#pragma unroll
                    for (int k = 0; k < 4; k++) {
                        float f = stage[r * SSTRIDE + lane + 32 * k];
                        stg_cs(fp + 32 * k, f);
                        stg_cs(yp + 32 * k, f);
                    }
                }
            }
            // mirror tile (off-diagonal only)
            if (!diag) {
#pragma unroll 1
                for (int it = 0; it < 16; it++) {
                    int r = it * 8 + cw;
                    uint32_t rowOff =
                        matBase + (uint32_t)(j0 + r) * T_ + (uint32_t)(i0 + lane);
                    float* fp = fcov + rowOff;
                    float* yp = ycov + rowOff;
#pragma unroll
                    for (int k = 0; k < 4; k++) {
                        float f = stage[(lane + 32 * k) * SSTRIDE + r];
                        stg_cs(fp + 32 * k, f);
                        stg_cs(yp + 32 * k, f);
                    }
                }
            }
            MBAR_ARRIVE(mb + 16 + 8 * s);     // empty[s]
            s ^= 1;
            if (s == 0) ph ^= 1;
        }
    }
}

// ---------------- launch ----------------
extern "C" void kernel_launch(void* const* d_in, const int* in_sizes, int n_in,
                              void* d_out, int out_size) {
    const float* in = (const float*)d_in[0];
    float* out = (float*)d_out;
    float* mean = out;
    float* fcov = out + (size_t)B_ * T_;
    float* ycov = fcov + (size_t)B_ * T_ * T_;

    pre_kernel<<<(B_ * T_ * 32 + 255) / 256, 256>>>(in, mean);

    static int smCount = 0;
    if (!smCount) {
        cudaDeviceGetAttribute(&smCount, cudaDevAttrMultiProcessorCount, 0);
        cudaFuncSetAttribute(cov_kernel, cudaFuncAttributeMaxDynamicSharedMemorySize,
                             SMEM_BYTES);
    }
    cov_kernel<<<smCount, 512, SMEM_BYTES>>>(in, fcov, ycov);
}

// round 10
// speedup vs baseline: 1.2338x; 1.1246x over previous
#include <cuda_runtime.h>
#include <cuda_fp16.h>
#include <math.h>
#include <stdint.h>

// ---------------- problem constants ----------------
#define B_ 4
#define T_ 4096
#define F_ 131           // 1 mean + 128 z + 1 v + 1 noise
#define D_ 128
#define TILE 128
#define NT 32            // T_/TILE
#define NPAIR 528        // NT*(NT+1)/2
#define JITTER_ 1e-6f

// per-row precomputed: w = exp(-sq/256)*v ; nsp = softplus(noise)
__device__ float g_w[B_ * T_];
__device__ float g_nsp[B_ * T_];

// ---------------- SMEM layout ----------------
// fp16 tiles: 128 rows x 136 halfs (272 B row stride)
#define TROW 136
#define TILE_BYTES (128 * TROW * 2)      // 34816
#define A_OFF 0
#define B_OFF TILE_BYTES
#define SMEM_BYTES (2 * TILE_BYTES)      // 69632
// mirror-transpose stage (reuses tile region): 128 x 132 floats = 67584 B
// stride 132: transposed STS conflict-free, row LDS.128 aligned+conflict-free
#define SSTRIDE 132

__device__ __forceinline__ uint32_t smem_u32(const void* p) {
    uint32_t a;
    asm("{ .reg .u64 t; cvta.to.shared.u64 t, %1; cvt.u32.u64 %0, t; }"
        : "=r"(a) : "l"(p));
    return a;
}

#define LDMX4(r0, r1, r2, r3, addr)                                        \
    asm volatile("ldmatrix.sync.aligned.m8n8.x4.shared.b16 {%0,%1,%2,%3}, [%4];" \
                 : "=r"(r0), "=r"(r1), "=r"(r2), "=r"(r3) : "r"(addr))

#define MMA16816(c, a0, a1, a2, a3, b0, b1)                                \
    asm volatile(                                                          \
        "mma.sync.aligned.m16n8k16.row.col.f32.f16.f16.f32 "               \
        "{%0,%1,%2,%3}, {%4,%5,%6,%7}, {%8,%9}, {%0,%1,%2,%3};"            \
        : "+f"((c)[0]), "+f"((c)[1]), "+f"((c)[2]), "+f"((c)[3])           \
        : "r"(a0), "r"(a1), "r"(a2), "r"(a3), "r"(b0), "r"(b1))

__device__ __forceinline__ void stg_cs2(float* p, float v0, float v1) {
    asm volatile("st.global.cs.v2.f32 [%0], {%1, %2};"
                 :: "l"(p), "f"(v0), "f"(v1) : "memory");
}
__device__ __forceinline__ void stg_cs4(float* p, float4 v) {
    asm volatile("st.global.cs.v4.f32 [%0], {%1, %2, %3, %4};"
                 :: "l"(p), "f"(v.x), "f"(v.y), "f"(v.z), "f"(v.w) : "memory");
}

__device__ __forceinline__ float ex2f(float x) {
    float y;
    asm("ex2.approx.ftz.f32 %0, %1;" : "=f"(y) : "f"(x));
    return y;
}

__device__ __forceinline__ uint32_t pack_h2(float x0, float x1) {
    __half h0 = __float2half_rn(x0);
    __half h1 = __float2half_rn(x1);
    return (uint32_t)__half_as_ushort(h0) | ((uint32_t)__half_as_ushort(h1) << 16);
}

// ---------------- prologue ----------------
__global__ void __launch_bounds__(256) pre_kernel(const float* __restrict__ in,
                                                  float* __restrict__ mean_out) {
    int warp = (blockIdx.x * blockDim.x + threadIdx.x) >> 5;
    int lane = threadIdx.x & 31;
    if (warp >= B_ * T_) return;
    const float* row = in + (size_t)warp * F_;
    float s = 0.f;
#pragma unroll
    for (int k = 0; k < 4; k++) {
        float z = row[1 + lane + 32 * k];
        s += z * z;
    }
#pragma unroll
    for (int off = 16; off; off >>= 1) s += __shfl_xor_sync(0xffffffffu, s, off);
    if (lane == 0) {
        float v = row[1 + D_];
        float noise = row[F_ - 1];
        g_w[warp] = exp2f(-s * 0.0056355275034725f) * v;  // exp(-s/256)*v
        g_nsp[warp] = fmaxf(noise, 0.f) + log1pf(__expf(-fabsf(noise)));
        mean_out[warp] = row[0];
    }
}

// ---------------- main kernel ----------------
extern __shared__ char smem[];

__global__ void __launch_bounds__(256, 2) cov_kernel(const float* __restrict__ in,
                                                     float* __restrict__ fcov,
                                                     float* __restrict__ ycov) {
    const int b = blockIdx.y;
    int u = blockIdx.x;
    int ti = 0;
    while (u >= NT - ti) { u -= NT - ti; ti++; }
    const int tj = ti + u;
    const int i0 = ti * TILE, j0 = tj * TILE;
    const bool diag = (ti == tj);

    const int tid = threadIdx.x;
    const int wid = tid >> 5;
    const int lane = tid & 31;
    const uint32_t sb = smem_u32(smem);

    // ---- load + fp16 convert into SMEM ----
    const float* base = in + (size_t)b * T_ * F_;
#pragma unroll 4
    for (int it = 0; it < 32; it++) {
        int p = it * 256 + tid;          // 0..8191 (128 rows x 64 col-pairs)
        int r = p >> 6;
        int c2 = (p & 63) * 2;
        uint32_t soff = (uint32_t)(r * (TROW * 2) + c2 * 2);
        {
            const float* rp = base + (uint32_t)((i0 + r) * F_ + 1 + c2);
            *(uint32_t*)(smem + A_OFF + soff) = pack_h2(__ldg(rp), __ldg(rp + 1));
        }
        {
            const float* rp = base + (uint32_t)((j0 + r) * F_ + 1 + c2);
            *(uint32_t*)(smem + B_OFF + soff) = pack_h2(__ldg(rp), __ldg(rp + 1));
        }
    }
    __syncthreads();

    // ---- MMA: D = A . B^T (fp16 x fp16 -> fp32) ----
    const int m0 = (wid & 3) * 32;
    const int n0 = (wid >> 2) * 64;

    float acc[2][8][4];
#pragma unroll
    for (int a = 0; a < 2; a++)
#pragma unroll
        for (int n = 0; n < 8; n++)
#pragma unroll
            for (int q = 0; q < 4; q++) acc[a][n][q] = 0.f;

    const uint32_t aRowByte = (uint32_t)((m0 + (lane & 15)) * (TROW * 2) +
                                         ((lane >> 4) * 8) * 2);
    const uint32_t bRowByte =
        (uint32_t)((n0 + (lane & 7) + ((lane >> 4) << 3)) * (TROW * 2) +
                   (((lane >> 3) & 1) * 8) * 2);

#pragma unroll 1
    for (int ks = 0; ks < 8; ks++) {
        const uint32_t koff = (uint32_t)(ks * 32);
        uint32_t ra[2][4];
#pragma unroll
        for (int a = 0; a < 2; a++) {
            uint32_t addr = sb + A_OFF + aRowByte + a * 16 * (TROW * 2) + koff;
            LDMX4(ra[a][0], ra[a][1], ra[a][2], ra[a][3], addr);
        }
#pragma unroll
        for (int nt = 0; nt < 4; nt++) {
            uint32_t rb[4];
            uint32_t addr = sb + B_OFF + bRowByte + nt * 16 * (TROW * 2) + koff;
            LDMX4(rb[0], rb[1], rb[2], rb[3], addr);
#pragma unroll
            for (int a = 0; a < 2; a++) {
                MMA16816(acc[a][2 * nt], ra[a][0], ra[a][1], ra[a][2], ra[a][3],
                         rb[0], rb[1]);
                MMA16816(acc[a][2 * nt + 1], ra[a][0], ra[a][1], ra[a][2],
                         ra[a][3], rb[2], rb[3]);
            }
        }
    }
    __syncthreads();   // tiles consumed; stage region is free

    // ---- fused epilogue: compute f, store direct tile from registers,
    //      stash transposed copy into SMEM stage for the mirror tile ----
    const int bT = b * T_;
    const float SC = 0.011271055006945f;  // log2(e)/128
    float* stage = (float*)smem;          // [128 cols][132] transposed
    const uint32_t matBase = (uint32_t)b * (uint32_t)(T_ * T_);

    const int rA = lane >> 2;             // 0..7
    const int cQ = 2 * (lane & 3);        // 0,2,4,6

    float wi[2][2], nspI[2][2], wj[8][2];
#pragma unroll
    for (int a = 0; a < 2; a++)
#pragma unroll
        for (int h = 0; h < 2; h++) {
            int rg = bT + i0 + m0 + a * 16 + rA + h * 8;
            wi[a][h] = __ldg(g_w + rg);
            nspI[a][h] = diag ? __ldg(g_nsp + rg) : 0.f;
        }
#pragma unroll
    for (int n = 0; n < 8; n++)
#pragma unroll
        for (int e = 0; e < 2; e++)
            wj[n][e] = __ldg(g_w + bT + j0 + n0 + n * 8 + cQ + e);

#pragma unroll
    for (int a = 0; a < 2; a++) {
#pragma unroll
        for (int n = 0; n < 8; n++) {
            float f[4];
#pragma unroll
            for (int q = 0; q < 4; q++)
                f[q] = ex2f(acc[a][n][q] * SC) * wi[a][q >> 1] * wj[n][q & 1];

            const int r1 = m0 + a * 16 + rA;       // local rows
            const int r2 = r1 + 8;
            const int c = n0 + n * 8 + cQ;          // local col (even)

            uint32_t off1 = matBase + (uint32_t)(i0 + r1) * T_ + (uint32_t)(j0 + c);
            uint32_t off2 = matBase + (uint32_t)(i0 + r2) * T_ + (uint32_t)(j0 + c);
            if (diag) {
                float f0 = f[0], f1 = f[1], f2 = f[2], f3 = f[3];
                float y0 = f0, y1 = f1, y2 = f2, y3 = f3;
                if (r1 == c)     { f0 += JITTER_; y0 += JITTER_ + nspI[a][0]; }
                if (r1 == c + 1) { f1 += JITTER_; y1 += JITTER_ + nspI[a][0]; }
                if (r2 == c)     { f2 += JITTER_; y2 += JITTER_ + nspI[a][1]; }
                if (r2 == c + 1) { f3 += JITTER_; y3 += JITTER_ + nspI[a][1]; }
                stg_cs2(fcov + off1, f0, f1);
                stg_cs2(ycov + off1, y0, y1);
                stg_cs2(fcov + off2, f2, f3);
                stg_cs2(ycov + off2, y2, y3);
            } else {
                stg_cs2(fcov + off1, f[0], f[1]);
                stg_cs2(ycov + off1, f[0], f[1]);
                stg_cs2(fcov + off2, f[2], f[3]);
                stg_cs2(ycov + off2, f[2], f[3]);
                // transposed stash: stage[col][row]  (conflict-free STS)
                stage[c * SSTRIDE + r1] = f[0];
                stage[(c + 1) * SSTRIDE + r1] = f[1];
                stage[c * SSTRIDE + r2] = f[2];
                stage[(c + 1) * SSTRIDE + r2] = f[3];
            }
        }
    }

    // ---- mirror tile (off-diagonal only): vector LDS.128 + STG.128 ----
    if (!diag) {
        __syncthreads();
#pragma unroll 2
        for (int it = 0; it < 16; it++) {
            int r = it * 8 + wid;   // mirror row (= original column)
            float4 v = *(const float4*)(stage + r * SSTRIDE + 4 * lane);
            uint32_t rowOff =
                matBase + (uint32_t)(j0 + r) * T_ + (uint32_t)(i0 + 4 * lane);
            stg_cs4(fcov + rowOff, v);
            stg_cs4(ycov + rowOff, v);
        }
    }
}

// ---------------- launch ----------------
extern "C" void kernel_launch(void* const* d_in, const int* in_sizes, int n_in,
                              void* d_out, int out_size) {
    const float* in = (const float*)d_in[0];
    float* out = (float*)d_out;
    float* mean = out;
    float* fcov = out + (size_t)B_ * T_;
    float* ycov = fcov + (size_t)B_ * T_ * T_;

    pre_kernel<<<(B_ * T_ * 32 + 255) / 256, 256>>>(in, mean);

    static int configured = 0;
    if (!configured) {
        cudaFuncSetAttribute(cov_kernel, cudaFuncAttributeMaxDynamicSharedMemorySize,
                             SMEM_BYTES);
        configured = 1;
    }
    dim3 grid(NPAIR, B_);
    cov_kernel<<<grid, 256, SMEM_BYTES>>>(in, fcov, ycov);
}